// round 4
// baseline (speedup 1.0000x reference)
#include <cuda_runtime.h>

// Problem constants (fixed by the reference setup)
#define NN 262144
#define EE 4194304
#define HID 32
#define LYR 4

// ---------------- device scratch (static, no allocation) ----------------
__device__ int   g_deg[NN];
__device__ int   g_offs[NN];       // exclusive prefix (also partials in-place)
__device__ int   g_cursor[NN];
__device__ int   g_blocksum[256];
__device__ int   g_csr[EE];        // src ids grouped by dst
__device__ float g_h0[NN * 16];    // layer-0 input, padded 9 -> 16
__device__ float g_hA[NN * 32];
__device__ float g_hB[NN * 32];
__device__ float g_z[NN * 32];     // pre-BN MLP output
__device__ float g_acc[NN * 8];    // running cat(xs) @ lin_W + lin_b
__device__ float g_stats[LYR * 64]; // per layer: sum[32], sumsq[32]

// ---------------- init: h0 build + zero deg + zero stats ----------------
__global__ void k_init(const float* __restrict__ x, const float* __restrict__ t) {
    int idx = blockIdx.x * blockDim.x + threadIdx.x;
    if (idx < NN * 16) {
        int i = idx >> 4, c = idx & 15;
        float v = 0.f;
        if (c < 8)       v = x[i * 8 + c];
        else if (c == 8) v = t[0];
        g_h0[idx] = v;
    }
    if (idx < NN) g_deg[idx] = 0;
    if (idx < LYR * 64) g_stats[idx] = 0.f;
}

// ---------------- CSR build ----------------
__global__ void k_hist(const int* __restrict__ ei) {
    int e = blockIdx.x * blockDim.x + threadIdx.x;
    if (e < EE) atomicAdd(&g_deg[ei[EE + e]], 1);
}

// phase 1: per-1024 block exclusive scan (256 blocks x 1024 threads)
__global__ void k_scan1() {
    int tid = threadIdx.x, lane = tid & 31, wid = tid >> 5;
    int g = blockIdx.x * 1024 + tid;
    int v = g_deg[g];
    int xv = v;
#pragma unroll
    for (int off = 1; off < 32; off <<= 1) {
        int y = __shfl_up_sync(0xffffffffu, xv, off);
        if (lane >= off) xv += y;
    }
    __shared__ int wt[32];
    if (lane == 31) wt[wid] = xv;
    __syncthreads();
    if (wid == 0) {
        int w = wt[lane];
        int xi = w;
#pragma unroll
        for (int off = 1; off < 32; off <<= 1) {
            int y = __shfl_up_sync(0xffffffffu, xi, off);
            if (lane >= off) xi += y;
        }
        wt[lane] = xi - w;                 // exclusive warp-total
        if (lane == 31) g_blocksum[blockIdx.x] = xi;
    }
    __syncthreads();
    g_offs[g] = (xv - v) + wt[wid];
}

// phase 2: scan of 256 block sums (1 block x 256 threads)
__global__ void k_scan2() {
    int tid = threadIdx.x, lane = tid & 31, wid = tid >> 5;
    int v = g_blocksum[tid];
    int xv = v;
#pragma unroll
    for (int off = 1; off < 32; off <<= 1) {
        int y = __shfl_up_sync(0xffffffffu, xv, off);
        if (lane >= off) xv += y;
    }
    __shared__ int wt[8];
    if (lane == 31) wt[wid] = xv;
    __syncthreads();
    if (tid == 0) {
        int s = 0;
        for (int i = 0; i < 8; i++) { int t0 = wt[i]; wt[i] = s; s += t0; }
    }
    __syncthreads();
    int out = (xv - v) + wt[wid];
    __syncthreads();
    g_blocksum[tid] = out;
}

// phase 3: add block offsets, init cursor
__global__ void k_scan3() {
    int g = blockIdx.x * blockDim.x + threadIdx.x;
    if (g < NN) {
        int o = g_offs[g] + g_blocksum[g >> 10];
        g_offs[g] = o;
        g_cursor[g] = o;
    }
}

__global__ void k_fill(const int* __restrict__ ei) {
    int e = blockIdx.x * blockDim.x + threadIdx.x;
    if (e < EE) {
        int d = ei[EE + e];
        int p = atomicAdd(&g_cursor[d], 1);
        g_csr[p] = ei[e];
    }
}

// ---------------- fused GIN layer: aggregate + combine + MLP + BN stats ----------------
// warp per node; lane = feature column. STRIDE = row stride of h_in (16 or 32).
template <int STRIDE>
__global__ __launch_bounds__(256) void k_gin(
    const float* __restrict__ h_in, float* __restrict__ z_out,
    const float* __restrict__ W1, int w1rows,
    const float* __restrict__ b1,
    const float* __restrict__ W2, const float* __restrict__ b2,
    const float* __restrict__ eps_p, int layer)
{
    __shared__ float w1s[STRIDE * 32];
    __shared__ float w2s[32 * 32];
    __shared__ float b1s[32], b2s[32];
    __shared__ float rs[8][32], rq[8][32];

    int tid = threadIdx.x;
    for (int i = tid; i < STRIDE * 32; i += blockDim.x) {
        int r = i >> 5;
        w1s[i] = (r < w1rows) ? W1[i] : 0.f;
    }
    for (int i = tid; i < 1024; i += blockDim.x) w2s[i] = W2[i];
    if (tid < 32) { b1s[tid] = b1[tid]; b2s[tid] = b2[tid]; }
    float epsv = 1.0f + eps_p[layer];
    __syncthreads();

    int lane = tid & 31, wid = tid >> 5;
    int w  = blockIdx.x * (blockDim.x >> 5) + wid;
    int nw = gridDim.x * (blockDim.x >> 5);
    float ssum = 0.f, ssq = 0.f;
    const bool active = (STRIDE == 32) || (lane < 16);

    for (int i = w; i < NN; i += nw) {
        float self = active ? h_in[i * STRIDE + lane] : 0.f;
        float acc = epsv * self;

        int start = g_offs[i];
        int end   = (i + 1 < NN) ? g_offs[i + 1] : EE;
        for (int j0 = start; j0 < end; j0 += 32) {
            int myj = j0 + lane;
            int idx = (myj < end) ? g_csr[myj] : 0;
            int cnt = min(32, end - j0);
            float a0 = 0.f, a1 = 0.f, a2 = 0.f, a3 = 0.f;
            int k = 0;
            for (; k + 4 <= cnt; k += 4) {
                int s0 = __shfl_sync(0xffffffffu, idx, k);
                int s1 = __shfl_sync(0xffffffffu, idx, k + 1);
                int s2 = __shfl_sync(0xffffffffu, idx, k + 2);
                int s3 = __shfl_sync(0xffffffffu, idx, k + 3);
                if (active) {
                    a0 += __ldg(&h_in[s0 * STRIDE + lane]);
                    a1 += __ldg(&h_in[s1 * STRIDE + lane]);
                    a2 += __ldg(&h_in[s2 * STRIDE + lane]);
                    a3 += __ldg(&h_in[s3 * STRIDE + lane]);
                }
            }
            for (; k < cnt; k++) {
                int s0 = __shfl_sync(0xffffffffu, idx, k);
                if (active) a0 += __ldg(&h_in[s0 * STRIDE + lane]);
            }
            acc += (a0 + a1) + (a2 + a3);
        }

        // MLP: hidden = relu(acc @ W1 + b1); o = hidden @ W2 + b2
        float hid = b1s[lane];
#pragma unroll
        for (int c = 0; c < STRIDE; c++)
            hid = fmaf(__shfl_sync(0xffffffffu, acc, c), w1s[c * 32 + lane], hid);
        hid = fmaxf(hid, 0.f);
        float o = b2s[lane];
#pragma unroll
        for (int c = 0; c < 32; c++)
            o = fmaf(__shfl_sync(0xffffffffu, hid, c), w2s[c * 32 + lane], o);
        z_out[i * 32 + lane] = o;
        ssum += o;
        ssq  = fmaf(o, o, ssq);
    }

    rs[wid][lane] = ssum;
    rq[wid][lane] = ssq;
    __syncthreads();
    if (wid == 0) {
        float s = 0.f, q = 0.f;
#pragma unroll
        for (int ww = 0; ww < 8; ww++) { s += rs[ww][lane]; q += rq[ww][lane]; }
        atomicAdd(&g_stats[layer * 64 + lane], s);
        atomicAdd(&g_stats[layer * 64 + 32 + lane], q);
    }
}

// ---------------- BN apply + ReLU + incremental final linear ----------------
__global__ __launch_bounds__(256) void k_bn(
    const float* __restrict__ z, float* __restrict__ h_out,
    const float* __restrict__ gamma, const float* __restrict__ beta,
    const float* __restrict__ linW, const float* __restrict__ lin_b,
    int layer)
{
    __shared__ float sc[32], bi[32], lw[256];
    int tid = threadIdx.x;
    if (tid < 32) {
        float s = g_stats[layer * 64 + tid];
        float q = g_stats[layer * 64 + 32 + tid];
        float mu  = s * (1.0f / NN);
        float var = q * (1.0f / NN) - mu * mu;
        float inv = rsqrtf(var + 1e-5f);
        float g = gamma[layer * 32 + tid] * inv;
        sc[tid] = g;
        bi[tid] = beta[layer * 32 + tid] - mu * g;
    }
    for (int i = tid; i < 256; i += blockDim.x) lw[i] = linW[layer * 256 + i];
    __syncthreads();

    int lane = tid & 31, wid = tid >> 5;
    int w  = blockIdx.x * (blockDim.x >> 5) + wid;
    int nw = gridDim.x * (blockDim.x >> 5);
    for (int i = w; i < NN; i += nw) {
        float zv = z[i * 32 + lane];
        float h = fmaxf(fmaf(zv, sc[lane], bi[lane]), 0.f);
        h_out[i * 32 + lane] = h;
        float od[8];
#pragma unroll
        for (int d = 0; d < 8; d++) {
            float p = h * lw[lane * 8 + d];
#pragma unroll
            for (int off = 16; off; off >>= 1)
                p += __shfl_xor_sync(0xffffffffu, p, off);
            od[d] = p;
        }
        if (lane < 8) {
            float v = od[lane];
            if (layer == 0) v += lin_b[lane];
            else            v += g_acc[i * 8 + lane];
            g_acc[i * 8 + lane] = v;
        }
    }
}

// ---------------- masked write-back ----------------
// Masks arrive as int32 (harness converts jax bool -> int32).
__global__ void k_mask(const float* __restrict__ x,
                       const int* __restrict__ nm,
                       const int* __restrict__ em,
                       float* __restrict__ out)
{
    int idx = blockIdx.x * blockDim.x + threadIdx.x;
    if (idx < NN * 8) {
        int i = idx >> 3, c = idx & 7;
        // ond = 5 -> node cols 1..5 ; oed = 4 -> edge cols 1..4 (fixed by setup)
        bool wn = (nm[i] != 0) && (c >= 1 && c <= 5);
        bool we = (em[i] != 0) && (c >= 1 && c <= 4);
        out[idx] = (wn || we) ? g_acc[idx] : x[idx];
    }
}

// ---------------- launch ----------------
extern "C" void kernel_launch(void* const* d_in, const int* in_sizes, int n_in,
                              void* d_out, int out_size)
{
    const float* x        = (const float*)d_in[0];
    const float* t        = (const float*)d_in[1];
    const int*   ei       = (const int*)d_in[2];
    const int*   node_mask = (const int*)d_in[3];
    const int*   edge_mask = (const int*)d_in[4];
    // d_in[5] = ond (5), d_in[6] = oed (4): int32 scalars, hardcoded
    const float* W1_first = (const float*)d_in[7];
    const float* b1_first = (const float*)d_in[8];
    const float* W2_first = (const float*)d_in[9];
    const float* b2_first = (const float*)d_in[10];
    const float* W1_rest  = (const float*)d_in[11];
    const float* b1_rest  = (const float*)d_in[12];
    const float* W2_rest  = (const float*)d_in[13];
    const float* b2_rest  = (const float*)d_in[14];
    const float* eps      = (const float*)d_in[15];
    const float* bn_gamma = (const float*)d_in[16];
    const float* bn_beta  = (const float*)d_in[17];
    const float* lin_W    = (const float*)d_in[18];
    const float* lin_b    = (const float*)d_in[19];
    float* out = (float*)d_out;

    // init + CSR build
    k_init<<<(NN * 16 + 255) / 256, 256>>>(x, t);
    k_hist<<<(EE + 255) / 256, 256>>>(ei);
    k_scan1<<<256, 1024>>>();
    k_scan2<<<1, 256>>>();
    k_scan3<<<(NN + 255) / 256, 256>>>();
    k_fill<<<(EE + 255) / 256, 256>>>(ei);

    const int GB = 148 * 8;  // grid for warp-per-node kernels

    {
        float* h0; cudaGetSymbolAddress((void**)&h0, g_h0);
        float* zz; cudaGetSymbolAddress((void**)&zz, g_z);
        float* hA; cudaGetSymbolAddress((void**)&hA, g_hA);
        float* hB; cudaGetSymbolAddress((void**)&hB, g_hB);

        k_gin<16><<<GB, 256>>>(h0, zz, W1_first, 9, b1_first, W2_first, b2_first, eps, 0);
        k_bn<<<GB, 256>>>(zz, hA, bn_gamma, bn_beta, lin_W, lin_b, 0);

        // Layers 1..3
        k_gin<32><<<GB, 256>>>(hA, zz, W1_rest + 0 * 1024, 32, b1_rest + 0 * 32,
                               W2_rest + 0 * 1024, b2_rest + 0 * 32, eps, 1);
        k_bn<<<GB, 256>>>(zz, hB, bn_gamma, bn_beta, lin_W, lin_b, 1);

        k_gin<32><<<GB, 256>>>(hB, zz, W1_rest + 1 * 1024, 32, b1_rest + 1 * 32,
                               W2_rest + 1 * 1024, b2_rest + 1 * 32, eps, 2);
        k_bn<<<GB, 256>>>(zz, hA, bn_gamma, bn_beta, lin_W, lin_b, 2);

        k_gin<32><<<GB, 256>>>(hA, zz, W1_rest + 2 * 1024, 32, b1_rest + 2 * 32,
                               W2_rest + 2 * 1024, b2_rest + 2 * 32, eps, 3);
        k_bn<<<GB, 256>>>(zz, hB, bn_gamma, bn_beta, lin_W, lin_b, 3);
    }

    k_mask<<<(NN * 8 + 255) / 256, 256>>>(x, node_mask, edge_mask, out);
}

// round 5
// speedup vs baseline: 1.0604x; 1.0604x over previous
#include <cuda_runtime.h>

// Problem constants (fixed by the reference setup)
#define NN 262144
#define EE 4194304
#define HID 32
#define LYR 4
#define FULLM 0xffffffffu

// ---------------- device scratch (static, no allocation) ----------------
__device__ int   g_deg[NN];
__device__ int   g_offs[NN];
__device__ int   g_cursor[NN];
__device__ int   g_blocksum[256];
__device__ int   g_csr[EE];
__device__ __align__(16) float g_h0[NN * 16];   // layer-0 input, padded 9 -> 16
__device__ __align__(16) float g_hA[NN * 32];
__device__ __align__(16) float g_hB[NN * 32];
__device__ __align__(16) float g_z[NN * 32];
__device__ __align__(16) float g_acc[NN * 8];
__device__ float g_stats[LYR * 64];

// ---------------- init ----------------
__global__ void k_init(const float* __restrict__ x, const float* __restrict__ t) {
    int idx = blockIdx.x * blockDim.x + threadIdx.x;
    if (idx < NN * 16) {
        int i = idx >> 4, c = idx & 15;
        float v = 0.f;
        if (c < 8)       v = x[i * 8 + c];
        else if (c == 8) v = t[0];
        g_h0[idx] = v;
    }
    if (idx < NN) g_deg[idx] = 0;
    if (idx < LYR * 64) g_stats[idx] = 0.f;
}

// ---------------- CSR build ----------------
__global__ void k_hist(const int* __restrict__ ei) {
    int e = blockIdx.x * blockDim.x + threadIdx.x;
    if (e < EE) atomicAdd(&g_deg[ei[EE + e]], 1);
}

__global__ void k_scan1() {
    int tid = threadIdx.x, lane = tid & 31, wid = tid >> 5;
    int g = blockIdx.x * 1024 + tid;
    int v = g_deg[g];
    int xv = v;
#pragma unroll
    for (int off = 1; off < 32; off <<= 1) {
        int y = __shfl_up_sync(FULLM, xv, off);
        if (lane >= off) xv += y;
    }
    __shared__ int wt[32];
    if (lane == 31) wt[wid] = xv;
    __syncthreads();
    if (wid == 0) {
        int w = wt[lane];
        int xi = w;
#pragma unroll
        for (int off = 1; off < 32; off <<= 1) {
            int y = __shfl_up_sync(FULLM, xi, off);
            if (lane >= off) xi += y;
        }
        wt[lane] = xi - w;
        if (lane == 31) g_blocksum[blockIdx.x] = xi;
    }
    __syncthreads();
    g_offs[g] = (xv - v) + wt[wid];
}

__global__ void k_scan2() {
    int tid = threadIdx.x, lane = tid & 31, wid = tid >> 5;
    int v = g_blocksum[tid];
    int xv = v;
#pragma unroll
    for (int off = 1; off < 32; off <<= 1) {
        int y = __shfl_up_sync(FULLM, xv, off);
        if (lane >= off) xv += y;
    }
    __shared__ int wt[8];
    if (lane == 31) wt[wid] = xv;
    __syncthreads();
    if (tid == 0) {
        int s = 0;
        for (int i = 0; i < 8; i++) { int t0 = wt[i]; wt[i] = s; s += t0; }
    }
    __syncthreads();
    int out = (xv - v) + wt[wid];
    __syncthreads();
    g_blocksum[tid] = out;
}

__global__ void k_scan3() {
    int g = blockIdx.x * blockDim.x + threadIdx.x;
    if (g < NN) {
        int o = g_offs[g] + g_blocksum[g >> 10];
        g_offs[g] = o;
        g_cursor[g] = o;
    }
}

__global__ void k_fill(const int* __restrict__ ei) {
    int e = blockIdx.x * blockDim.x + threadIdx.x;
    if (e < EE) {
        int d = ei[EE + e];
        int p = atomicAdd(&g_cursor[d], 1);
        g_csr[p] = ei[e];
    }
}

// ---------------- fused GIN layer ----------------
// Warp per node. Gather: warp split into G=128/STRIDE groups of ROWF4=STRIDE/4
// lanes; each group fetches one neighbor row as float4 (LDG.128) -> G edges per
// warp instruction, 2x unrolled (2G edges in flight). Partials folded via
// float4 xor-shuffle; MLP reads features via component-indexed shuffles.
template <int STRIDE>
__global__ __launch_bounds__(256) void k_gin(
    const float* __restrict__ h_in, float* __restrict__ z_out,
    const float* __restrict__ W1, int w1rows,
    const float* __restrict__ b1,
    const float* __restrict__ W2, const float* __restrict__ b2,
    const float* __restrict__ eps_p, int layer)
{
    constexpr int ROWF4 = STRIDE / 4;     // float4 lanes per row (4 or 8)
    constexpr int G     = 32 / ROWF4;     // edges gathered per instruction (8 or 4)

    __shared__ float w1s[STRIDE * 32];
    __shared__ float w2s[32 * 32];
    __shared__ float b1s[32], b2s[32];
    __shared__ float rs[8][32], rq[8][32];

    int tid = threadIdx.x;
    for (int i = tid; i < STRIDE * 32; i += blockDim.x) {
        int r = i >> 5;
        w1s[i] = (r < w1rows) ? W1[i] : 0.f;
    }
    for (int i = tid; i < 1024; i += blockDim.x) w2s[i] = W2[i];
    if (tid < 32) { b1s[tid] = b1[tid]; b2s[tid] = b2[tid]; }
    float epsv = 1.0f + eps_p[layer];
    __syncthreads();

    int lane = tid & 31, wid = tid >> 5;
    int grp  = lane / ROWF4;              // group id (edge slot)
    int r    = lane & (ROWF4 - 1);        // float4 index within row
    int w  = blockIdx.x * (blockDim.x >> 5) + wid;
    int nw = gridDim.x * (blockDim.x >> 5);
    float ssum = 0.f, ssq = 0.f;

    const float4* hin4 = (const float4*)h_in;

    for (int i = w; i < NN; i += nw) {
        // self term: only group 0 contributes (avoid G-fold duplication)
        float4 self4 = __ldg(&hin4[i * ROWF4 + r]);
        float4 accA, accB;
        if (grp == 0) {
            accA.x = epsv * self4.x; accA.y = epsv * self4.y;
            accA.z = epsv * self4.z; accA.w = epsv * self4.w;
        } else {
            accA.x = accA.y = accA.z = accA.w = 0.f;
        }
        accB.x = accB.y = accB.z = accB.w = 0.f;

        int start = g_offs[i];
        int end   = (i + 1 < NN) ? g_offs[i + 1] : EE;

        for (int j0 = start; j0 < end; j0 += 32) {
            int myj = j0 + lane;
            int idx = (myj < end) ? g_csr[myj] : 0;
            int cnt = min(32, end - j0);
            int k = 0;
            for (; k + 2 * G <= cnt; k += 2 * G) {
                int s0 = __shfl_sync(FULLM, idx, k + grp);
                int s1 = __shfl_sync(FULLM, idx, k + G + grp);
                float4 v0 = __ldg(&hin4[s0 * ROWF4 + r]);
                float4 v1 = __ldg(&hin4[s1 * ROWF4 + r]);
                accA.x += v0.x; accA.y += v0.y; accA.z += v0.z; accA.w += v0.w;
                accB.x += v1.x; accB.y += v1.y; accB.z += v1.z; accB.w += v1.w;
            }
            for (; k < cnt; k += G) {
                int e = k + grp;
                int s = __shfl_sync(FULLM, idx, e & 31);
                if (e < cnt) {
                    float4 v = __ldg(&hin4[s * ROWF4 + r]);
                    accA.x += v.x; accA.y += v.y; accA.z += v.z; accA.w += v.w;
                }
            }
        }
        accA.x += accB.x; accA.y += accB.y; accA.z += accB.z; accA.w += accB.w;

        // fold groups: after xor-reduce every lane holds the total for its r
#pragma unroll
        for (int off = ROWF4; off < 32; off <<= 1) {
            accA.x += __shfl_xor_sync(FULLM, accA.x, off);
            accA.y += __shfl_xor_sync(FULLM, accA.y, off);
            accA.z += __shfl_xor_sync(FULLM, accA.z, off);
            accA.w += __shfl_xor_sync(FULLM, accA.w, off);
        }

        // MLP: hidden = relu(acc @ W1 + b1); o = hidden @ W2 + b2
        // feature c lives in lane (c>>2) component (c&3)
        float hid = b1s[lane];
#pragma unroll
        for (int c = 0; c < STRIDE; c++) {
            float av;
            switch (c & 3) {
                case 0: av = __shfl_sync(FULLM, accA.x, c >> 2); break;
                case 1: av = __shfl_sync(FULLM, accA.y, c >> 2); break;
                case 2: av = __shfl_sync(FULLM, accA.z, c >> 2); break;
                default: av = __shfl_sync(FULLM, accA.w, c >> 2); break;
            }
            hid = fmaf(av, w1s[c * 32 + lane], hid);
        }
        hid = fmaxf(hid, 0.f);
        float o = b2s[lane];
#pragma unroll
        for (int c = 0; c < 32; c++)
            o = fmaf(__shfl_sync(FULLM, hid, c), w2s[c * 32 + lane], o);
        z_out[i * 32 + lane] = o;
        ssum += o;
        ssq  = fmaf(o, o, ssq);
    }

    rs[wid][lane] = ssum;
    rq[wid][lane] = ssq;
    __syncthreads();
    if (wid == 0) {
        float s = 0.f, q = 0.f;
#pragma unroll
        for (int ww = 0; ww < 8; ww++) { s += rs[ww][lane]; q += rq[ww][lane]; }
        atomicAdd(&g_stats[layer * 64 + lane], s);
        atomicAdd(&g_stats[layer * 64 + 32 + lane], q);
    }
}

// ---------------- BN apply + ReLU + incremental final linear ----------------
__global__ __launch_bounds__(256) void k_bn(
    const float* __restrict__ z, float* __restrict__ h_out,
    const float* __restrict__ gamma, const float* __restrict__ beta,
    const float* __restrict__ linW, const float* __restrict__ lin_b,
    int layer)
{
    __shared__ float sc[32], bi[32], lw[256];
    int tid = threadIdx.x;
    if (tid < 32) {
        float s = g_stats[layer * 64 + tid];
        float q = g_stats[layer * 64 + 32 + tid];
        float mu  = s * (1.0f / NN);
        float var = q * (1.0f / NN) - mu * mu;
        float inv = rsqrtf(var + 1e-5f);
        float g = gamma[layer * 32 + tid] * inv;
        sc[tid] = g;
        bi[tid] = beta[layer * 32 + tid] - mu * g;
    }
    for (int i = tid; i < 256; i += blockDim.x) lw[i] = linW[layer * 256 + i];
    __syncthreads();

    int lane = tid & 31, wid = tid >> 5;
    int w  = blockIdx.x * (blockDim.x >> 5) + wid;
    int nw = gridDim.x * (blockDim.x >> 5);
    for (int i = w; i < NN; i += nw) {
        float zv = z[i * 32 + lane];
        float h = fmaxf(fmaf(zv, sc[lane], bi[lane]), 0.f);
        h_out[i * 32 + lane] = h;
        float od[8];
#pragma unroll
        for (int d = 0; d < 8; d++) {
            float p = h * lw[lane * 8 + d];
#pragma unroll
            for (int off = 16; off; off >>= 1)
                p += __shfl_xor_sync(FULLM, p, off);
            od[d] = p;
        }
        if (lane < 8) {
            float v = od[lane];
            if (layer == 0) v += lin_b[lane];
            else            v += g_acc[i * 8 + lane];
            g_acc[i * 8 + lane] = v;
        }
    }
}

// ---------------- masked write-back (masks are int32) ----------------
__global__ void k_mask(const float* __restrict__ x,
                       const int* __restrict__ nm,
                       const int* __restrict__ em,
                       float* __restrict__ out)
{
    int idx = blockIdx.x * blockDim.x + threadIdx.x;
    if (idx < NN * 8) {
        int i = idx >> 3, c = idx & 7;
        bool wn = (nm[i] != 0) && (c >= 1 && c <= 5);
        bool we = (em[i] != 0) && (c >= 1 && c <= 4);
        out[idx] = (wn || we) ? g_acc[idx] : x[idx];
    }
}

// ---------------- launch ----------------
extern "C" void kernel_launch(void* const* d_in, const int* in_sizes, int n_in,
                              void* d_out, int out_size)
{
    const float* x        = (const float*)d_in[0];
    const float* t        = (const float*)d_in[1];
    const int*   ei       = (const int*)d_in[2];
    const int*   node_mask = (const int*)d_in[3];
    const int*   edge_mask = (const int*)d_in[4];
    const float* W1_first = (const float*)d_in[7];
    const float* b1_first = (const float*)d_in[8];
    const float* W2_first = (const float*)d_in[9];
    const float* b2_first = (const float*)d_in[10];
    const float* W1_rest  = (const float*)d_in[11];
    const float* b1_rest  = (const float*)d_in[12];
    const float* W2_rest  = (const float*)d_in[13];
    const float* b2_rest  = (const float*)d_in[14];
    const float* eps      = (const float*)d_in[15];
    const float* bn_gamma = (const float*)d_in[16];
    const float* bn_beta  = (const float*)d_in[17];
    const float* lin_W    = (const float*)d_in[18];
    const float* lin_b    = (const float*)d_in[19];
    float* out = (float*)d_out;

    k_init<<<(NN * 16 + 255) / 256, 256>>>(x, t);
    k_hist<<<(EE + 255) / 256, 256>>>(ei);
    k_scan1<<<256, 1024>>>();
    k_scan2<<<1, 256>>>();
    k_scan3<<<(NN + 255) / 256, 256>>>();
    k_fill<<<(EE + 255) / 256, 256>>>(ei);

    const int GB = 148 * 8;

    {
        float* h0; cudaGetSymbolAddress((void**)&h0, g_h0);
        float* zz; cudaGetSymbolAddress((void**)&zz, g_z);
        float* hA; cudaGetSymbolAddress((void**)&hA, g_hA);
        float* hB; cudaGetSymbolAddress((void**)&hB, g_hB);

        k_gin<16><<<GB, 256>>>(h0, zz, W1_first, 9, b1_first, W2_first, b2_first, eps, 0);
        k_bn<<<GB, 256>>>(zz, hA, bn_gamma, bn_beta, lin_W, lin_b, 0);

        k_gin<32><<<GB, 256>>>(hA, zz, W1_rest + 0 * 1024, 32, b1_rest + 0 * 32,
                               W2_rest + 0 * 1024, b2_rest + 0 * 32, eps, 1);
        k_bn<<<GB, 256>>>(zz, hB, bn_gamma, bn_beta, lin_W, lin_b, 1);

        k_gin<32><<<GB, 256>>>(hB, zz, W1_rest + 1 * 1024, 32, b1_rest + 1 * 32,
                               W2_rest + 1 * 1024, b2_rest + 1 * 32, eps, 2);
        k_bn<<<GB, 256>>>(zz, hA, bn_gamma, bn_beta, lin_W, lin_b, 2);

        k_gin<32><<<GB, 256>>>(hA, zz, W1_rest + 2 * 1024, 32, b1_rest + 2 * 32,
                               W2_rest + 2 * 1024, b2_rest + 2 * 32, eps, 3);
        k_bn<<<GB, 256>>>(zz, hB, bn_gamma, bn_beta, lin_W, lin_b, 3);
    }

    k_mask<<<(NN * 8 + 255) / 256, 256>>>(x, node_mask, edge_mask, out);
}

// round 6
// speedup vs baseline: 1.2143x; 1.1451x over previous
#include <cuda_runtime.h>

// Problem constants (fixed by the reference setup)
#define NN 262144
#define EE 4194304
#define HID 32
#define LYR 4
#define FULLM 0xffffffffu

// ---------------- device scratch (static, no allocation) ----------------
__device__ int   g_deg[NN];
__device__ int   g_offs[NN];
__device__ int   g_cursor[NN];
__device__ int   g_blocksum[256];
__device__ int   g_csr[EE];
__device__ __align__(16) float g_h0[NN * 16];   // layer-0 input, padded 9 -> 16
__device__ __align__(16) float g_hA[NN * 32];
__device__ __align__(16) float g_hB[NN * 32];
__device__ __align__(16) float g_agg[NN * 32];  // aggregation output
__device__ __align__(16) float g_z[NN * 32];
__device__ __align__(16) float g_acc[NN * 8];
__device__ float g_stats[LYR * 64];

// ---------------- init: h0 build + deg hist + zero stats ----------------
// NN*16 == EE, so one grid covers both jobs.
__global__ void k_init(const float* __restrict__ x, const float* __restrict__ t,
                       const int* __restrict__ ei) {
    int idx = blockIdx.x * blockDim.x + threadIdx.x;
    if (idx < NN * 16) {
        int i = idx >> 4, c = idx & 15;
        float v = 0.f;
        if (c < 8)       v = x[i * 8 + c];
        else if (c == 8) v = t[0];
        g_h0[idx] = v;
    }
    if (idx < NN) g_deg[idx] = 0;
    if (idx < LYR * 64) g_stats[idx] = 0.f;
    __syncthreads();            // deg zeroing of this block's range done before...
    // NOTE: cross-block ordering of zero vs atomic is NOT guaranteed; so zero
    // must not race with hist. Avoid: zero deg for index idx<NN handled above,
    // but hist atomics target arbitrary nodes -> must be a separate pass.
}

__global__ void k_hist(const int* __restrict__ ei) {
    int e = blockIdx.x * blockDim.x + threadIdx.x;
    if (e < EE) atomicAdd(&g_deg[ei[EE + e]], 1);
}

// ---------------- CSR scan ----------------
__global__ void k_scan1() {
    int tid = threadIdx.x, lane = tid & 31, wid = tid >> 5;
    int g = blockIdx.x * 1024 + tid;
    int v = g_deg[g];
    int xv = v;
#pragma unroll
    for (int off = 1; off < 32; off <<= 1) {
        int y = __shfl_up_sync(FULLM, xv, off);
        if (lane >= off) xv += y;
    }
    __shared__ int wt[32];
    if (lane == 31) wt[wid] = xv;
    __syncthreads();
    if (wid == 0) {
        int w = wt[lane];
        int xi = w;
#pragma unroll
        for (int off = 1; off < 32; off <<= 1) {
            int y = __shfl_up_sync(FULLM, xi, off);
            if (lane >= off) xi += y;
        }
        wt[lane] = xi - w;
        if (lane == 31) g_blocksum[blockIdx.x] = xi;
    }
    __syncthreads();
    g_offs[g] = (xv - v) + wt[wid];
}

__global__ void k_scan2() {
    int tid = threadIdx.x, lane = tid & 31, wid = tid >> 5;
    int v = g_blocksum[tid];
    int xv = v;
#pragma unroll
    for (int off = 1; off < 32; off <<= 1) {
        int y = __shfl_up_sync(FULLM, xv, off);
        if (lane >= off) xv += y;
    }
    __shared__ int wt[8];
    if (lane == 31) wt[wid] = xv;
    __syncthreads();
    if (tid == 0) {
        int s = 0;
        for (int i = 0; i < 8; i++) { int t0 = wt[i]; wt[i] = s; s += t0; }
    }
    __syncthreads();
    int out = (xv - v) + wt[wid];
    __syncthreads();
    g_blocksum[tid] = out;
}

__global__ void k_scan3() {
    int g = blockIdx.x * blockDim.x + threadIdx.x;
    if (g < NN) {
        int o = g_offs[g] + g_blocksum[g >> 10];
        g_offs[g] = o;
        g_cursor[g] = o;
    }
}

__global__ void k_fill(const int* __restrict__ ei) {
    int e = blockIdx.x * blockDim.x + threadIdx.x;
    if (e < EE) {
        int d = ei[EE + e];
        int p = atomicAdd(&g_cursor[d], 1);
        g_csr[p] = ei[e];
    }
}

// ---------------- aggregation only: agg[i] = (1+eps)*h[i] + sum_{j->i} h[j] --
// Warp per node; G groups of ROWF4 lanes each fetch one float4 row-slice.
template <int STRIDE>
__global__ __launch_bounds__(256) void k_agg(
    const float* __restrict__ h_in, float* __restrict__ agg_out,
    const float* __restrict__ eps_p, int layer)
{
    constexpr int ROWF4 = STRIDE / 4;
    constexpr int G     = 32 / ROWF4;
    float epsv = 1.0f + eps_p[layer];

    int tid = threadIdx.x;
    int lane = tid & 31, wid = tid >> 5;
    int grp  = lane / ROWF4;
    int r    = lane & (ROWF4 - 1);
    int w  = blockIdx.x * (blockDim.x >> 5) + wid;
    int nw = gridDim.x * (blockDim.x >> 5);

    const float4* hin4 = (const float4*)h_in;
    float4* agg4 = (float4*)agg_out;

    for (int i = w; i < NN; i += nw) {
        float4 accA, accB;
        if (grp == 0) {
            float4 s4 = __ldg(&hin4[i * ROWF4 + r]);
            accA.x = epsv * s4.x; accA.y = epsv * s4.y;
            accA.z = epsv * s4.z; accA.w = epsv * s4.w;
        } else {
            accA.x = accA.y = accA.z = accA.w = 0.f;
        }
        accB.x = accB.y = accB.z = accB.w = 0.f;

        int start = g_offs[i];
        int end   = (i + 1 < NN) ? g_offs[i + 1] : EE;

        for (int j0 = start; j0 < end; j0 += 32) {
            int myj = j0 + lane;
            int idx = (myj < end) ? g_csr[myj] : 0;
            int cnt = min(32, end - j0);
            int k = 0;
            for (; k + 2 * G <= cnt; k += 2 * G) {
                int s0 = __shfl_sync(FULLM, idx, k + grp);
                int s1 = __shfl_sync(FULLM, idx, k + G + grp);
                float4 v0 = __ldg(&hin4[s0 * ROWF4 + r]);
                float4 v1 = __ldg(&hin4[s1 * ROWF4 + r]);
                accA.x += v0.x; accA.y += v0.y; accA.z += v0.z; accA.w += v0.w;
                accB.x += v1.x; accB.y += v1.y; accB.z += v1.z; accB.w += v1.w;
            }
            for (; k < cnt; k += G) {
                int e = k + grp;
                int s = __shfl_sync(FULLM, idx, e & 31);
                if (e < cnt) {
                    float4 v = __ldg(&hin4[s * ROWF4 + r]);
                    accA.x += v.x; accA.y += v.y; accA.z += v.z; accA.w += v.w;
                }
            }
        }
        accA.x += accB.x; accA.y += accB.y; accA.z += accB.z; accA.w += accB.w;

#pragma unroll
        for (int off = ROWF4; off < 32; off <<= 1) {
            accA.x += __shfl_xor_sync(FULLM, accA.x, off);
            accA.y += __shfl_xor_sync(FULLM, accA.y, off);
            accA.z += __shfl_xor_sync(FULLM, accA.z, off);
            accA.w += __shfl_xor_sync(FULLM, accA.w, off);
        }
        if (grp == 0) agg4[i * ROWF4 + r] = accA;   // coalesced STG.128
    }
}

// ---------------- MLP + BN stats: z = relu(agg@W1+b1)@W2+b2 -----------------
// Warp per node; lane = output channel; weights in registers.
template <int STRIDE>
__global__ __launch_bounds__(256) void k_mlp(
    const float* __restrict__ agg, float* __restrict__ z_out,
    const float* __restrict__ W1, int w1rows, const float* __restrict__ b1,
    const float* __restrict__ W2, const float* __restrict__ b2, int layer)
{
    __shared__ float hs[8][32];
    __shared__ float rs[8][32], rq[8][32];

    int tid = threadIdx.x;
    int lane = tid & 31, wid = tid >> 5;

    float w1r[STRIDE], w2r[32];
#pragma unroll
    for (int c = 0; c < STRIDE; c++)
        w1r[c] = (c < w1rows) ? __ldg(&W1[c * 32 + lane]) : 0.f;
#pragma unroll
    for (int c = 0; c < 32; c++)
        w2r[c] = __ldg(&W2[c * 32 + lane]);
    float b1v = __ldg(&b1[lane]);
    float b2v = __ldg(&b2[lane]);

    int w  = blockIdx.x * (blockDim.x >> 5) + wid;
    int nw = gridDim.x * (blockDim.x >> 5);
    float ssum = 0.f, ssq = 0.f;

    const float4* agg4 = (const float4*)agg;

    for (int i = w; i < NN; i += nw) {
        // broadcast agg row via uniform LDG.128 (all lanes same address)
        float hid = b1v;
#pragma unroll
        for (int q = 0; q < STRIDE / 4; q++) {
            float4 a = __ldg(&agg4[i * (STRIDE / 4) + q]);
            hid = fmaf(a.x, w1r[4 * q + 0], hid);
            hid = fmaf(a.y, w1r[4 * q + 1], hid);
            hid = fmaf(a.z, w1r[4 * q + 2], hid);
            hid = fmaf(a.w, w1r[4 * q + 3], hid);
        }
        hid = fmaxf(hid, 0.f);

        hs[wid][lane] = hid;
        __syncwarp();
        float o = b2v;
        const float4* hrow = (const float4*)&hs[wid][0];
#pragma unroll
        for (int q = 0; q < 8; q++) {
            float4 hq = hrow[q];
            o = fmaf(hq.x, w2r[4 * q + 0], o);
            o = fmaf(hq.y, w2r[4 * q + 1], o);
            o = fmaf(hq.z, w2r[4 * q + 2], o);
            o = fmaf(hq.w, w2r[4 * q + 3], o);
        }
        __syncwarp();
        z_out[i * 32 + lane] = o;
        ssum += o;
        ssq  = fmaf(o, o, ssq);
    }

    rs[wid][lane] = ssum;
    rq[wid][lane] = ssq;
    __syncthreads();
    if (wid == 0) {
        float s = 0.f, q = 0.f;
#pragma unroll
        for (int ww = 0; ww < 8; ww++) { s += rs[ww][lane]; q += rq[ww][lane]; }
        atomicAdd(&g_stats[layer * 64 + lane], s);
        atomicAdd(&g_stats[layer * 64 + 32 + lane], q);
    }
}

// ---------------- BN apply + ReLU + incremental final linear ----------------
__global__ __launch_bounds__(256) void k_bn(
    const float* __restrict__ z, float* __restrict__ h_out,
    const float* __restrict__ gamma, const float* __restrict__ beta,
    const float* __restrict__ linW, const float* __restrict__ lin_b,
    int layer)
{
    __shared__ float sc[32], bi[32], lw[256];
    int tid = threadIdx.x;
    if (tid < 32) {
        float s = g_stats[layer * 64 + tid];
        float q = g_stats[layer * 64 + 32 + tid];
        float mu  = s * (1.0f / NN);
        float var = q * (1.0f / NN) - mu * mu;
        float inv = rsqrtf(var + 1e-5f);
        float g = gamma[layer * 32 + tid] * inv;
        sc[tid] = g;
        bi[tid] = beta[layer * 32 + tid] - mu * g;
    }
    for (int i = tid; i < 256; i += blockDim.x) lw[i] = linW[layer * 256 + i];
    __syncthreads();

    int lane = tid & 31, wid = tid >> 5;
    int w  = blockIdx.x * (blockDim.x >> 5) + wid;
    int nw = gridDim.x * (blockDim.x >> 5);
    for (int i = w; i < NN; i += nw) {
        float zv = z[i * 32 + lane];
        float h = fmaxf(fmaf(zv, sc[lane], bi[lane]), 0.f);
        h_out[i * 32 + lane] = h;
        float od[8];
#pragma unroll
        for (int d = 0; d < 8; d++) {
            float p = h * lw[lane * 8 + d];
#pragma unroll
            for (int off = 16; off; off >>= 1)
                p += __shfl_xor_sync(FULLM, p, off);
            od[d] = p;
        }
        if (lane < 8) {
            float v = od[lane];
            if (layer == 0) v += lin_b[lane];
            else            v += g_acc[i * 8 + lane];
            g_acc[i * 8 + lane] = v;
        }
    }
}

// ---------------- masked write-back (masks are int32) ----------------
__global__ void k_mask(const float* __restrict__ x,
                       const int* __restrict__ nm,
                       const int* __restrict__ em,
                       float* __restrict__ out)
{
    int idx = blockIdx.x * blockDim.x + threadIdx.x;
    if (idx < NN * 8) {
        int i = idx >> 3, c = idx & 7;
        bool wn = (nm[i] != 0) && (c >= 1 && c <= 5);
        bool we = (em[i] != 0) && (c >= 1 && c <= 4);
        out[idx] = (wn || we) ? g_acc[idx] : x[idx];
    }
}

// ---------------- launch ----------------
extern "C" void kernel_launch(void* const* d_in, const int* in_sizes, int n_in,
                              void* d_out, int out_size)
{
    const float* x        = (const float*)d_in[0];
    const float* t        = (const float*)d_in[1];
    const int*   ei       = (const int*)d_in[2];
    const int*   node_mask = (const int*)d_in[3];
    const int*   edge_mask = (const int*)d_in[4];
    const float* W1_first = (const float*)d_in[7];
    const float* b1_first = (const float*)d_in[8];
    const float* W2_first = (const float*)d_in[9];
    const float* b2_first = (const float*)d_in[10];
    const float* W1_rest  = (const float*)d_in[11];
    const float* b1_rest  = (const float*)d_in[12];
    const float* W2_rest  = (const float*)d_in[13];
    const float* b2_rest  = (const float*)d_in[14];
    const float* eps      = (const float*)d_in[15];
    const float* bn_gamma = (const float*)d_in[16];
    const float* bn_beta  = (const float*)d_in[17];
    const float* lin_W    = (const float*)d_in[18];
    const float* lin_b    = (const float*)d_in[19];
    float* out = (float*)d_out;

    k_init<<<(NN * 16 + 255) / 256, 256>>>(x, t, ei);
    k_hist<<<(EE + 255) / 256, 256>>>(ei);
    k_scan1<<<256, 1024>>>();
    k_scan2<<<1, 256>>>();
    k_scan3<<<(NN + 255) / 256, 256>>>();
    k_fill<<<(EE + 255) / 256, 256>>>(ei);

    const int GB = 148 * 8;

    float* h0; cudaGetSymbolAddress((void**)&h0, g_h0);
    float* ag; cudaGetSymbolAddress((void**)&ag, g_agg);
    float* zz; cudaGetSymbolAddress((void**)&zz, g_z);
    float* hA; cudaGetSymbolAddress((void**)&hA, g_hA);
    float* hB; cudaGetSymbolAddress((void**)&hB, g_hB);

    // Layer 0
    k_agg<16><<<GB, 256>>>(h0, ag, eps, 0);
    k_mlp<16><<<GB, 256>>>(ag, zz, W1_first, 9, b1_first, W2_first, b2_first, 0);
    k_bn<<<GB, 256>>>(zz, hA, bn_gamma, bn_beta, lin_W, lin_b, 0);

    // Layer 1
    k_agg<32><<<GB, 256>>>(hA, ag, eps, 1);
    k_mlp<32><<<GB, 256>>>(ag, zz, W1_rest + 0 * 1024, 32, b1_rest + 0 * 32,
                           W2_rest + 0 * 1024, b2_rest + 0 * 32, 1);
    k_bn<<<GB, 256>>>(zz, hB, bn_gamma, bn_beta, lin_W, lin_b, 1);

    // Layer 2
    k_agg<32><<<GB, 256>>>(hB, ag, eps, 2);
    k_mlp<32><<<GB, 256>>>(ag, zz, W1_rest + 1 * 1024, 32, b1_rest + 1 * 32,
                           W2_rest + 1 * 1024, b2_rest + 1 * 32, 2);
    k_bn<<<GB, 256>>>(zz, hA, bn_gamma, bn_beta, lin_W, lin_b, 2);

    // Layer 3
    k_agg<32><<<GB, 256>>>(hA, ag, eps, 3);
    k_mlp<32><<<GB, 256>>>(ag, zz, W1_rest + 2 * 1024, 32, b1_rest + 2 * 32,
                           W2_rest + 2 * 1024, b2_rest + 2 * 32, 3);
    k_bn<<<GB, 256>>>(zz, hB, bn_gamma, bn_beta, lin_W, lin_b, 3);

    k_mask<<<(NN * 8 + 255) / 256, 256>>>(x, node_mask, edge_mask, out);
}